// round 5
// baseline (speedup 1.0000x reference)
#include <cuda_runtime.h>
#include <math.h>

#define NH   64
#define NI   128
#define NHID 512
#define NO   256
#define NS   4
#define EPS_GN 1e-5f
#define TINY 1e-14f

#define NBLK 148
#define TPB  512
#define NWARP (NBLK * (TPB / 32))   // 2368

// ---------------- scratch (device globals: no allocation allowed) ----------
__device__ float g_sub[NH * NI];        // (H, n_inp), flat index == h*128+r
__device__ float g_lastprod[NO];
__device__ float g_t1[NH * NHID];       // raw w1@sub
__device__ float g_h1[NH * NHID];       // softplus(GN(t1))
__device__ float g_z[NS * NH * NO];     // raw w2@h1
__device__ float g_psm[NS * NH * NO];   // per-s softmax
__device__ float g_scalar[NH * NO];     // ws row sums

// ---------------- grid barrier (all 148 blocks resident) -------------------
__device__ unsigned g_bar_arrive = 0;
__device__ unsigned g_bar_gen = 0;

__device__ __forceinline__ void grid_sync() {
    __syncthreads();
    if (threadIdx.x == 0) {
        __threadfence();
        unsigned gen = *(volatile unsigned*)&g_bar_gen;   // read BEFORE arriving
        if (atomicAdd(&g_bar_arrive, 1u) == (unsigned)(gridDim.x - 1)) {
            g_bar_arrive = 0u;
            __threadfence();
            atomicAdd(&g_bar_gen, 1u);
        } else {
            while (*(volatile unsigned*)&g_bar_gen == gen) __nanosleep(32);
        }
        __threadfence();
    }
    __syncthreads();
}

// ---------------- helpers ----------------
__device__ __forceinline__ float warp_sum(float v) {
#pragma unroll
    for (int o = 16; o > 0; o >>= 1) v += __shfl_xor_sync(0xffffffffu, v, o);
    return v;
}
__device__ __forceinline__ float warp_max(float v) {
#pragma unroll
    for (int o = 16; o > 0; o >>= 1) v = fmaxf(v, __shfl_xor_sync(0xffffffffu, v, o));
    return v;
}
__device__ __forceinline__ float dot4(float4 a, float4 b) {
    return a.x * b.x + a.y * b.y + a.z * b.z + a.w * b.w;
}

// ---------------- the whole net, one persistent kernel ---------------------
__global__ __launch_bounds__(TPB, 1)
void fused_net(const float* __restrict__ x,
               const float* __restrict__ lsm,
               const float* __restrict__ qw,
               const float* __restrict__ w1,
               const float* __restrict__ g1,
               const float* __restrict__ b1,
               const float* __restrict__ w2,
               const float* __restrict__ g2,
               const float* __restrict__ b2,
               const float* __restrict__ ws,
               const float* __restrict__ woo,
               float* __restrict__ out) {
    const int tid  = threadIdx.x;
    const int lane = tid & 31;
    const int gw   = blockIdx.x * (TPB / 32) + (tid >> 5);   // 0..NWARP-1

    // ===== Phase 1: sub = x @ qw^T (per head), last_prod ====================
    // 8192 flat rows (h*128+r), chunks of 4 rows.
    for (int c = gw; c < 2048; c += NWARP) {
        const int row0 = c * 4;
        const int h = row0 >> 7;
        const float4 qv = __ldg((const float4*)(qw + h * NI) + lane);
        float4 xv[4];
#pragma unroll
        for (int u = 0; u < 4; u++) {
            const int r = (row0 + u) & (NI - 1);
            xv[u] = __ldg((const float4*)(x + (size_t)r * NI) + lane);
        }
#pragma unroll
        for (int u = 0; u < 4; u++) {
            float v = warp_sum(dot4(xv[u], qv));
            if (lane == 0) g_sub[row0 + u] = v;
        }
    }
    if (gw >= 2048 && gw < 2048 + 8) {
        const int o = (gw - 2048) * 32 + lane;
        float p = 1.f;
#pragma unroll 8
        for (int k = 0; k < NH; k++) p *= __ldg(lsm + o * NH + k);
        g_lastprod[o] = p;
    }
    grid_sync();

    // ===== Phase 2: t1 = w1 @ sub  AND  ws row sums (interleaved) ==========
    // t1: 32768 rows of 128 -> 8192 units of 4 rows (2 KB each)
    // ws: 16384 rows of 256 -> 8192 units of 2 rows (2 KB each)
    for (int u = gw; u < 16384; u += NWARP) {
        if (u < 8192) {
            const int row0 = u * 4;
            const int h = row0 >> 9;
            const float4 sv = ((const float4*)(g_sub + h * NI))[lane];
            const float4* base = (const float4*)w1 + (size_t)row0 * (NI / 4);
            float4 a[4];
#pragma unroll
            for (int r = 0; r < 4; r++)
                a[r] = __ldg(base + (size_t)r * (NI / 4) + lane);
#pragma unroll
            for (int r = 0; r < 4; r++) {
                float v = warp_sum(dot4(a[r], sv));
                if (lane == 0) g_t1[row0 + r] = v;
            }
        } else {
            const int row0 = (u - 8192) * 2;
            const float4* base = (const float4*)ws + (size_t)row0 * (NO / 4);
            float4 a0 = __ldg(base + lane),      a1 = __ldg(base + 32 + lane);
            float4 c0 = __ldg(base + 64 + lane), c1 = __ldg(base + 96 + lane);
            float v0 = warp_sum(a0.x + a0.y + a0.z + a0.w + a1.x + a1.y + a1.z + a1.w);
            float v1 = warp_sum(c0.x + c0.y + c0.z + c0.w + c1.x + c1.y + c1.z + c1.w);
            if (lane == 0) { g_scalar[row0] = v0; g_scalar[row0 + 1] = v1; }
        }
    }
    grid_sync();

    // ===== Phase 3: h1 = softplus(GN(t1)), warp per head ===================
    if (gw < NH) {
        const int h = gw;
        float t[16];
#pragma unroll
        for (int i = 0; i < 16; i++) t[i] = g_t1[h * NHID + lane + 32 * i];
        float s = 0.f;
#pragma unroll
        for (int i = 0; i < 16; i++) s += t[i];
        const float mu = warp_sum(s) * (1.f / NHID);
        float s2 = 0.f;
#pragma unroll
        for (int i = 0; i < 16; i++) { float d = t[i] - mu; s2 += d * d; }
        const float inv = rsqrtf(warp_sum(s2) * (1.f / NHID) + EPS_GN);
#pragma unroll
        for (int i = 0; i < 16; i++) {
            const int idx = h * NHID + lane + 32 * i;
            const float zn = (t[i] - mu) * inv * __ldg(g1 + idx) + __ldg(b1 + idx);
            g_h1[idx] = fmaxf(zn, 0.f) + log1pf(expf(-fabsf(zn)));
        }
    }
    grid_sync();

    // ===== Phase 4: z = w2 @ h1 (128 MB stream) ============================
    // 65536 rows of 512 -> 16384 units of 4 rows; 16 LDG.128 in flight/warp.
    for (int u = gw; u < 16384; u += NWARP) {
        const int row0 = u * 4;
        const int b = row0 >> 8;          // s*64+h
        const int h = b & 63;
        const float4* hb = (const float4*)(g_h1 + h * NHID);
        float4 hv[4];
#pragma unroll
        for (int k = 0; k < 4; k++) hv[k] = hb[k * 32 + lane];
        const float4* base = (const float4*)w2 + (size_t)row0 * (NHID / 4);
        float4 a[4][4];
#pragma unroll
        for (int r = 0; r < 4; r++)
#pragma unroll
            for (int k = 0; k < 4; k++)
                a[r][k] = __ldg(base + (size_t)r * (NHID / 4) + k * 32 + lane);
#pragma unroll
        for (int r = 0; r < 4; r++) {
            float v = dot4(a[r][0], hv[0]) + dot4(a[r][1], hv[1]) +
                      dot4(a[r][2], hv[2]) + dot4(a[r][3], hv[3]);
            v = warp_sum(v);
            if (lane == 0) g_z[row0 + r] = v;
        }
    }
    grid_sync();

    // ===== Phase 5a: GN + softmax per (s,h), warp per b ====================
    if (gw < NS * NH) {
        const int b = gw;
        float z[8];
#pragma unroll
        for (int i = 0; i < 8; i++) z[i] = g_z[b * NO + lane + 32 * i];
        float s = 0.f;
#pragma unroll
        for (int i = 0; i < 8; i++) s += z[i];
        const float mu = warp_sum(s) * (1.f / NO);
        float s2 = 0.f;
#pragma unroll
        for (int i = 0; i < 8; i++) { float d = z[i] - mu; s2 += d * d; }
        const float inv = rsqrtf(warp_sum(s2) * (1.f / NO) + EPS_GN);
        float zn[8];
        float mx = -INFINITY;
#pragma unroll
        for (int i = 0; i < 8; i++) {
            const int idx = b * NO + lane + 32 * i;
            zn[i] = (z[i] - mu) * inv * __ldg(g2 + idx) + __ldg(b2 + idx);
            mx = fmaxf(mx, zn[i]);
        }
        mx = warp_max(mx);
        float e[8], es = 0.f;
#pragma unroll
        for (int i = 0; i < 8; i++) { e[i] = expf(zn[i] - mx); es += e[i]; }
        es = warp_sum(es);
        const float r = 1.f / es;
#pragma unroll
        for (int i = 0; i < 8; i++) g_psm[b * NO + lane + 32 * i] = e[i] * r;
    }
    grid_sync();

    // ===== Phase 5b: gate + outputs, warp per head =========================
    if (gw < NH) {
        const int h = gw;
        float osm[8], part = 0.f;
#pragma unroll
        for (int i = 0; i < 8; i++) {
            const int o = lane + 32 * i;
            float v = 0.f;
#pragma unroll
            for (int s = 0; s < NS; s++) v += g_psm[(s * NH + h) * NO + o];
            osm[i] = v;
            part += __ldg(woo + h * 2 * NO + o) * g_lastprod[o] +
                    __ldg(woo + h * 2 * NO + NO + o) * v;
        }
        const float logit = warp_sum(part);
        const float on = 1.f / (1.f + expf(-logit));
#pragma unroll
        for (int i = 0; i < 8; i++) {
            const int o = lane + 32 * i;
            const float a = on * osm[i];
            out[o * NH + h] = fmaxf(a, TINY);
            const float v = a * g_scalar[h * NO + o];
            out[NO * NH + o * NH + h] = (fabsf(v) <= TINY) ? TINY : v;
        }
    }
}

// ---------------- launch ---------------------------------------------------
extern "C" void kernel_launch(void* const* d_in, const int* in_sizes, int n_in,
                              void* d_out, int out_size) {
    const float* x   = (const float*)d_in[0];
    const float* lsm = (const float*)d_in[1];
    const float* qw  = (const float*)d_in[2];
    const float* w1  = (const float*)d_in[3];
    const float* g1  = (const float*)d_in[4];
    const float* b1  = (const float*)d_in[5];
    const float* w2  = (const float*)d_in[6];
    const float* g2  = (const float*)d_in[7];
    const float* b2  = (const float*)d_in[8];
    const float* ws  = (const float*)d_in[9];
    const float* woo = (const float*)d_in[10];
    float* out = (float*)d_out;

    fused_net<<<NBLK, TPB>>>(x, lsm, qw, w1, g1, b1, w2, g2, b2, ws, woo, out);
}

// round 6
// speedup vs baseline: 1.2455x; 1.2455x over previous
#include <cuda_runtime.h>
#include <math.h>

#define NH   64
#define NI   128
#define NHID 512
#define NO   256
#define NS   4
#define EPS_GN 1e-5f
#define TINY 1e-14f

// ---------------- scratch (device globals: no allocation allowed) ----------
__device__ float g_sub[NH * NI];        // (H, n_inp)
__device__ float g_lastprod[NO];
__device__ float g_t1[NH * NHID];       // raw w1@sub
__device__ float g_h1[NH * NHID];       // softplus(GN(t1))
__device__ float g_z[NS * NH * NO];     // raw w2@h1
__device__ float g_scalar[NH * NO];     // ws row sums
__device__ int   g_cnt[NH];             // per-head arrival tickets (self-resetting)

// ---------------- helpers ----------------
__device__ __forceinline__ float warp_sum(float v) {
#pragma unroll
    for (int o = 16; o > 0; o >>= 1) v += __shfl_xor_sync(0xffffffffu, v, o);
    return v;
}
__device__ __forceinline__ float warp_max(float v) {
#pragma unroll
    for (int o = 16; o > 0; o >>= 1) v = fmaxf(v, __shfl_xor_sync(0xffffffffu, v, o));
    return v;
}
template <int NW>
__device__ __forceinline__ float block_sum(float v, float* red, int tid) {
    v = warp_sum(v);
    __syncthreads();
    if ((tid & 31) == 0) red[tid >> 5] = v;
    __syncthreads();
    float s = 0.f;
#pragma unroll
    for (int i = 0; i < NW; i++) s += red[i];
    return s;
}
__device__ __forceinline__ float dot4(float4 a, float4 b) {
    return a.x * b.x + a.y * b.y + a.z * b.z + a.w * b.w;
}

// ---------------- K1: sub = x @ qw^T per head; last_prod -------------------
// grid 65 x 256. Blocks 0..63: head h. Block 64: last_prod.
__global__ void K1(const float* __restrict__ x,
                   const float* __restrict__ qw,
                   const float* __restrict__ lsm) {
    const int tid = threadIdx.x, warp = tid >> 5, lane = tid & 31;
    if (blockIdx.x == NH) {
        const int o = tid;
        float p = 1.f;
#pragma unroll 8
        for (int k = 0; k < NH; k++) p *= __ldg(lsm + o * NH + k);
        g_lastprod[o] = p;
        return;
    }
    const int h = blockIdx.x;
    const float4 qv = __ldg((const float4*)(qw + h * NI) + lane);
    for (int r = warp; r < NI; r += 8) {
        float4 xv = __ldg((const float4*)(x + (size_t)r * NI) + lane);
        float v = warp_sum(dot4(xv, qv));
        if (lane == 0) g_sub[h * NI + r] = v;
    }
}

// ---------------- K2: t1 = w1 @ sub; last block per head does GN+softplus --
// grid 1024 x 256. Warp gw handles rows [4gw, 4gw+4). Block x covers rows
// [32x, 32x+32) -> 16 blocks per head; the 16th arrival runs GroupNorm.
__global__ void K2(const float* __restrict__ w1,
                   const float* __restrict__ g1,
                   const float* __restrict__ b1) {
    const int tid = threadIdx.x, warp = tid >> 5, lane = tid & 31;
    const int gw = blockIdx.x * 8 + warp;
    const int row0 = gw * 4;
    const int h = blockIdx.x >> 4;
    const float4 sv = ((const float4*)(g_sub + h * NI))[lane];
    const float4* base = (const float4*)w1 + (size_t)row0 * (NI / 4);
    float4 a[4];
#pragma unroll
    for (int r = 0; r < 4; r++) a[r] = __ldg(base + (size_t)r * (NI / 4) + lane);
#pragma unroll
    for (int r = 0; r < 4; r++) {
        float v = warp_sum(dot4(a[r], sv));
        if (lane == 0) g_t1[row0 + r] = v;
    }
    // ---- per-head completion ticket; last block computes GN + softplus ----
    __shared__ int s_last;
    __shared__ float red[8];
    __syncthreads();
    if (tid == 0) {
        __threadfence();
        s_last = (atomicAdd(&g_cnt[h], 1) == 15);
    }
    __syncthreads();
    if (s_last) {
        // 256 threads over 512 values: 2 per thread
        const float t0 = g_t1[h * NHID + tid];
        const float t1v = g_t1[h * NHID + 256 + tid];
        const float mu = block_sum<8>(t0 + t1v, red, tid) * (1.f / NHID);
        const float d0 = t0 - mu, d1 = t1v - mu;
        const float var = block_sum<8>(d0 * d0 + d1 * d1, red, tid) * (1.f / NHID);
        const float inv = rsqrtf(var + EPS_GN);
        const int i0 = h * NHID + tid, i1 = i0 + 256;
        const float z0 = d0 * inv * __ldg(g1 + i0) + __ldg(b1 + i0);
        const float z1 = d1 * inv * __ldg(g1 + i1) + __ldg(b1 + i1);
        g_h1[i0] = fmaxf(z0, 0.f) + log1pf(expf(-fabsf(z0)));
        g_h1[i1] = fmaxf(z1, 0.f) + log1pf(expf(-fabsf(z1)));
        if (tid == 0) g_cnt[h] = 0;   // reset for next graph replay
    }
}

// ---------------- K3: z = w2 @ h1  AND  ws row sums (one flat stream) ------
// grid 2560 x 256 -> 20480 warps, exactly one 4-row unit each.
// Units 0..16383: w2 rows (512 wide). Units 16384..20479: ws rows (256 wide).
__global__ void K3(const float* __restrict__ w2, const float* __restrict__ ws) {
    const int tid = threadIdx.x, warp = tid >> 5, lane = tid & 31;
    const int u = blockIdx.x * 8 + warp;
    if (u < 16384) {
        const int row0 = u * 4;
        const int h = (row0 >> 8) & 63;
        const float4* hb = (const float4*)(g_h1 + h * NHID);
        float4 hv[4];
#pragma unroll
        for (int k = 0; k < 4; k++) hv[k] = hb[k * 32 + lane];
        const float4* base = (const float4*)w2 + (size_t)row0 * (NHID / 4);
#pragma unroll
        for (int j = 0; j < 4; j += 2) {
            float4 a[2][4];
#pragma unroll
            for (int r = 0; r < 2; r++)
#pragma unroll
                for (int k = 0; k < 4; k++)
                    a[r][k] = __ldg(base + (size_t)(j + r) * (NHID / 4) + k * 32 + lane);
#pragma unroll
            for (int r = 0; r < 2; r++) {
                float v = dot4(a[r][0], hv[0]) + dot4(a[r][1], hv[1]) +
                          dot4(a[r][2], hv[2]) + dot4(a[r][3], hv[3]);
                v = warp_sum(v);
                if (lane == 0) g_z[row0 + j + r] = v;
            }
        }
    } else {
        const int row0 = (u - 16384) * 4;
        const float4* base = (const float4*)ws + (size_t)row0 * (NO / 4);
        float4 a[4][2];
#pragma unroll
        for (int r = 0; r < 4; r++) {
            a[r][0] = __ldg(base + (size_t)r * (NO / 4) + lane);
            a[r][1] = __ldg(base + (size_t)r * (NO / 4) + 32 + lane);
        }
#pragma unroll
        for (int r = 0; r < 4; r++) {
            float v = a[r][0].x + a[r][0].y + a[r][0].z + a[r][0].w +
                      a[r][1].x + a[r][1].y + a[r][1].z + a[r][1].w;
            v = warp_sum(v);
            if (lane == 0) g_scalar[row0 + r] = v;
        }
    }
}

// ---------------- K4: GN + softmax + gate + outputs ------------------------
// grid 64 (head) x 256 (one thread per n_out position).
__global__ void K4(const float* __restrict__ g2, const float* __restrict__ b2,
                   const float* __restrict__ woo, float* __restrict__ out) {
    const int h = blockIdx.x, o = threadIdx.x;
    __shared__ float red[8];
    float osm = 0.f;
#pragma unroll
    for (int s = 0; s < NS; s++) {
        const int b = s * NH + h;
        const float z = g_z[b * NO + o];
        const float mu = block_sum<8>(z, red, o) * (1.f / NO);
        const float d = z - mu;
        const float var = block_sum<8>(d * d, red, o) * (1.f / NO);
        const float zn = d * rsqrtf(var + EPS_GN) * __ldg(g2 + b * NO + o) + __ldg(b2 + b * NO + o);
        // block max
        float m = warp_max(zn);
        __syncthreads();
        if ((o & 31) == 0) red[o >> 5] = m;
        __syncthreads();
        float mx = -INFINITY;
#pragma unroll
        for (int i = 0; i < 8; i++) mx = fmaxf(mx, red[i]);
        const float e = expf(zn - mx);
        const float es = block_sum<8>(e, red, o);
        osm += e / es;
    }
    const float part = __ldg(woo + h * 2 * NO + o) * g_lastprod[o] +
                       __ldg(woo + h * 2 * NO + NO + o) * osm;
    const float logit = block_sum<8>(part, red, o);
    const float on = 1.f / (1.f + expf(-logit));
    const float a = on * osm;
    out[o * NH + h] = fmaxf(a, TINY);
    const float v = a * g_scalar[h * NO + o];
    out[NO * NH + o * NH + h] = (fabsf(v) <= TINY) ? TINY : v;
}

// ---------------- launch ---------------------------------------------------
extern "C" void kernel_launch(void* const* d_in, const int* in_sizes, int n_in,
                              void* d_out, int out_size) {
    const float* x   = (const float*)d_in[0];
    const float* lsm = (const float*)d_in[1];
    const float* qw  = (const float*)d_in[2];
    const float* w1  = (const float*)d_in[3];
    const float* g1  = (const float*)d_in[4];
    const float* b1  = (const float*)d_in[5];
    const float* w2  = (const float*)d_in[6];
    const float* g2  = (const float*)d_in[7];
    const float* b2  = (const float*)d_in[8];
    const float* ws  = (const float*)d_in[9];
    const float* woo = (const float*)d_in[10];
    float* out = (float*)d_out;

    K1<<<NH + 1, 256>>>(x, qw, lsm);          // sub + last_prod
    K2<<<1024, 256>>>(w1, g1, b1);            // t1 + fused GN/softplus -> h1
    K3<<<2560, 256>>>(w2, ws);                // z (128 MB) + ws sums (16 MB)
    K4<<<NH, 256>>>(g2, b2, woo, out);        // GN+softmax+gate+outputs
}